// round 2
// baseline (speedup 1.0000x reference)
#include <cuda_runtime.h>
#include <cuda_bf16.h>

// Problem constants (fixed by the dataset)
#define NN 100000
#define EE 1600000
#define DH 128

// ---------------- scratch (device globals; no allocation allowed) -------------
__device__ float g_agg[NN * DH];
__device__ float g_h1[NN * DH];
__device__ float g_h2[NN * DH];
__device__ int   g_counts[NN];
__device__ int   g_row[NN + 1];
__device__ int   g_cursor[NN];
__device__ int   g_csr[EE];
__device__ int   g_bsums[128];
__device__ int   g_boffs[128];
__device__ float g_invdeg[NN];
__device__ float g_pl[NN * 2];
__device__ float g_pr[NN * 2];

// ---------------- CSR build --------------------------------------------------
__global__ void k_zero_counts() {
    int i = blockIdx.x * blockDim.x + threadIdx.x;
    if (i < NN) g_counts[i] = 0;
}

__global__ void k_hist(const int* __restrict__ dst) {
    int e = blockIdx.x * blockDim.x + threadIdx.x;
    if (e < EE) atomicAdd(&g_counts[dst[e]], 1);
}

// scan phase 1: per-block exclusive scan of 1024 counts
__global__ void k_scan1() {
    __shared__ int sd[1024];
    int t = threadIdx.x;
    int g = blockIdx.x * 1024 + t;
    int v = (g < NN) ? g_counts[g] : 0;
    sd[t] = v;
    __syncthreads();
    #pragma unroll
    for (int off = 1; off < 1024; off <<= 1) {
        int x = (t >= off) ? sd[t - off] : 0;
        __syncthreads();
        sd[t] += x;
        __syncthreads();
    }
    if (g < NN) g_row[g] = sd[t] - v;   // exclusive
    if (t == 1023) g_bsums[blockIdx.x] = sd[t];
}

// scan phase 2: scan of per-block sums (98 blocks -> pad to 128)
__global__ void k_scan2(int nblk) {
    __shared__ int sd[128];
    int t = threadIdx.x;
    int v = (t < nblk) ? g_bsums[t] : 0;
    sd[t] = v;
    __syncthreads();
    #pragma unroll
    for (int off = 1; off < 128; off <<= 1) {
        int x = (t >= off) ? sd[t - off] : 0;
        __syncthreads();
        sd[t] += x;
        __syncthreads();
    }
    g_boffs[t] = sd[t] - v;             // exclusive
}

// scan phase 3: add block offsets, init cursor, inv_deg
__global__ void k_scan3() {
    int t = threadIdx.x;
    int g = blockIdx.x * 1024 + t;
    if (g < NN) {
        int r = g_row[g] + g_boffs[blockIdx.x];
        g_row[g] = r;
        g_cursor[g] = r;
        int c = g_counts[g];
        g_invdeg[g] = 1.0f / (float)(c > 0 ? c : 1);
    }
    if (blockIdx.x == 0 && t == 0) g_row[NN] = EE;
}

__global__ void k_scatter(const int* __restrict__ src, const int* __restrict__ dst) {
    int e = blockIdx.x * blockDim.x + threadIdx.x;
    if (e < EE) {
        int d = dst[e];
        int pos = atomicAdd(&g_cursor[d], 1);
        g_csr[pos] = src[e];
    }
}

// ---------------- mean aggregation (128-dim), warp per dst node ---------------
__global__ void k_agg128(const float* __restrict__ hin, float* __restrict__ aggout) {
    int warp = (blockIdx.x * blockDim.x + threadIdx.x) >> 5;
    int lane = threadIdx.x & 31;
    if (warp >= NN) return;
    int s0 = g_row[warp];
    int s1 = g_row[warp + 1];
    float4 acc0 = make_float4(0.f, 0.f, 0.f, 0.f);
    float4 acc1 = make_float4(0.f, 0.f, 0.f, 0.f);
    int e = s0;
    for (; e + 1 < s1; e += 2) {
        int a = g_csr[e];
        int b = g_csr[e + 1];
        float4 va = *(const float4*)(hin + (size_t)a * DH + lane * 4);
        float4 vb = *(const float4*)(hin + (size_t)b * DH + lane * 4);
        acc0.x += va.x; acc0.y += va.y; acc0.z += va.z; acc0.w += va.w;
        acc1.x += vb.x; acc1.y += vb.y; acc1.z += vb.z; acc1.w += vb.w;
    }
    if (e < s1) {
        int a = g_csr[e];
        float4 va = *(const float4*)(hin + (size_t)a * DH + lane * 4);
        acc0.x += va.x; acc0.y += va.y; acc0.z += va.z; acc0.w += va.w;
    }
    float sc = g_invdeg[warp];
    float4 o;
    o.x = (acc0.x + acc1.x) * sc;
    o.y = (acc0.y + acc1.y) * sc;
    o.z = (acc0.z + acc1.z) * sc;
    o.w = (acc0.w + acc1.w) * sc;
    *(float4*)(aggout + (size_t)warp * DH + lane * 4) = o;
}

// ---------------- fused layer GEMM: out = act(agg@Wl^T + b + hin@Wr^T) --------
// K = 256 (concat agg|hin). Weights transposed in smem with padded stride 132.
#define WSTRIDE 132
#define GEMM_BM 64

template <bool RELU>
__global__ void k_gemm(const float* __restrict__ agg, const float* __restrict__ hin,
                       const float* __restrict__ wl, const float* __restrict__ wr,
                       const float* __restrict__ bias, float* __restrict__ hout) {
    extern __shared__ float sm[];
    float* sW = sm;                         // [256][WSTRIDE]
    float* sX = sm + 256 * WSTRIDE;         // [GEMM_BM][256]
    int tid = threadIdx.x;

    // stage weights transposed: sW[k][j] = wl[j][k] (k<128) / wr[j][k-128]
    for (int i = tid; i < 128 * 128; i += 256) {
        int j = i >> 7, k = i & 127;
        sW[k * WSTRIDE + j] = wl[i];
        sW[(k + 128) * WSTRIDE + j] = wr[i];
    }

    int nodeBase = blockIdx.x * GEMM_BM;
    // stage inputs: rows [agg | hin]
    for (int i = tid; i < GEMM_BM * 32; i += 256) {
        int r = i >> 5, c4 = (i & 31) * 4;
        int n = nodeBase + r;
        float4 va = make_float4(0.f, 0.f, 0.f, 0.f);
        float4 vh = va;
        if (n < NN) {
            va = *(const float4*)(agg + (size_t)n * DH + c4);
            vh = *(const float4*)(hin + (size_t)n * DH + c4);
        }
        *(float4*)&sX[r * 256 + c4] = va;
        *(float4*)&sX[r * 256 + 128 + c4] = vh;
    }
    __syncthreads();

    int tx = tid & 31;    // feature group: outputs [4tx, 4tx+3]
    int ty = tid >> 5;    // node group: nodes [8ty, 8ty+7]

    float acc[8][4];
    #pragma unroll
    for (int t = 0; t < 8; t++)
        #pragma unroll
        for (int q = 0; q < 4; q++) acc[t][q] = 0.f;

    #pragma unroll 4
    for (int k = 0; k < 256; k++) {
        float4 bv = *(const float4*)&sW[k * WSTRIDE + tx * 4];
        #pragma unroll
        for (int t = 0; t < 8; t++) {
            float a = sX[(ty * 8 + t) * 256 + k];
            acc[t][0] += a * bv.x;
            acc[t][1] += a * bv.y;
            acc[t][2] += a * bv.z;
            acc[t][3] += a * bv.w;
        }
    }

    float4 bb = *(const float4*)&bias[tx * 4];
    #pragma unroll
    for (int t = 0; t < 8; t++) {
        int n = nodeBase + ty * 8 + t;
        if (n < NN) {
            float4 o;
            o.x = acc[t][0] + bb.x;
            o.y = acc[t][1] + bb.y;
            o.z = acc[t][2] + bb.z;
            o.w = acc[t][3] + bb.w;
            if (RELU) {
                o.x = fmaxf(o.x, 0.f); o.y = fmaxf(o.y, 0.f);
                o.z = fmaxf(o.z, 0.f); o.w = fmaxf(o.w, 0.f);
            }
            *(float4*)(hout + (size_t)n * DH + tx * 4) = o;
        }
    }
}

// ---------------- layer 2: project h2 -> [N,2] for both paths -----------------
__global__ void k_proj2(const float* __restrict__ h2, const float* __restrict__ wl2,
                        const float* __restrict__ wr2) {
    int warp = (blockIdx.x * blockDim.x + threadIdx.x) >> 5;
    int lane = threadIdx.x & 31;
    if (warp >= NN) return;
    float4 hv = *(const float4*)(h2 + (size_t)warp * DH + lane * 4);
    float4 a0 = *(const float4*)(wl2 + lane * 4);
    float4 a1 = *(const float4*)(wl2 + 128 + lane * 4);
    float4 r0 = *(const float4*)(wr2 + lane * 4);
    float4 r1 = *(const float4*)(wr2 + 128 + lane * 4);
    float d0 = hv.x * a0.x + hv.y * a0.y + hv.z * a0.z + hv.w * a0.w;
    float d1 = hv.x * a1.x + hv.y * a1.y + hv.z * a1.z + hv.w * a1.w;
    float d2 = hv.x * r0.x + hv.y * r0.y + hv.z * r0.z + hv.w * r0.w;
    float d3 = hv.x * r1.x + hv.y * r1.y + hv.z * r1.z + hv.w * r1.w;
    #pragma unroll
    for (int o = 16; o; o >>= 1) {
        d0 += __shfl_xor_sync(0xffffffffu, d0, o);
        d1 += __shfl_xor_sync(0xffffffffu, d1, o);
        d2 += __shfl_xor_sync(0xffffffffu, d2, o);
        d3 += __shfl_xor_sync(0xffffffffu, d3, o);
    }
    if (lane == 0) {
        g_pl[warp * 2 + 0] = d0;
        g_pl[warp * 2 + 1] = d1;
        g_pr[warp * 2 + 0] = d2;
        g_pr[warp * 2 + 1] = d3;
    }
}

// ---------------- layer 2 aggregation (2-dim) + bias + log_softmax ------------
__global__ void k_final(const float* __restrict__ b2, float* __restrict__ out) {
    int warp = (blockIdx.x * blockDim.x + threadIdx.x) >> 5;
    int lane = threadIdx.x & 31;
    if (warp >= NN) return;
    int s0 = g_row[warp];
    int s1 = g_row[warp + 1];
    float a0 = 0.f, a1 = 0.f;
    for (int e = s0 + lane; e < s1; e += 32) {
        int s = g_csr[e];
        float2 v = *(const float2*)&g_pl[s * 2];
        a0 += v.x;
        a1 += v.y;
    }
    #pragma unroll
    for (int o = 16; o; o >>= 1) {
        a0 += __shfl_xor_sync(0xffffffffu, a0, o);
        a1 += __shfl_xor_sync(0xffffffffu, a1, o);
    }
    if (lane == 0) {
        float inv = g_invdeg[warp];
        float o0 = a0 * inv + b2[0] + g_pr[warp * 2 + 0];
        float o1 = a1 * inv + b2[1] + g_pr[warp * 2 + 1];
        float m = fmaxf(o0, o1);
        float ls = m + logf(expf(o0 - m) + expf(o1 - m));
        out[warp * 2 + 0] = o0 - ls;
        out[warp * 2 + 1] = o1 - ls;
    }
}

// ---------------- launch -----------------------------------------------------
extern "C" void kernel_launch(void* const* d_in, const int* in_sizes, int n_in,
                              void* d_out, int out_size) {
    const float* x    = (const float*)d_in[0];
    const float* wl0  = (const float*)d_in[1];
    const float* b0   = (const float*)d_in[2];
    const float* wr0  = (const float*)d_in[3];
    const float* wl1  = (const float*)d_in[4];
    const float* b1   = (const float*)d_in[5];
    const float* wr1  = (const float*)d_in[6];
    const float* wl2  = (const float*)d_in[7];
    const float* b2   = (const float*)d_in[8];
    const float* wr2  = (const float*)d_in[9];
    const int* esrc   = (const int*)d_in[10];
    const int* edst   = (const int*)d_in[11];
    float* out        = (float*)d_out;

    float* agg; cudaGetSymbolAddress((void**)&agg, g_agg);
    float* h1;  cudaGetSymbolAddress((void**)&h1, g_h1);
    float* h2;  cudaGetSymbolAddress((void**)&h2, g_h2);

    const int nblk_scan = (NN + 1023) / 1024;        // 98
    const int gemm_smem = (256 * WSTRIDE + GEMM_BM * 256) * (int)sizeof(float);
    cudaFuncSetAttribute(k_gemm<true>, cudaFuncAttributeMaxDynamicSharedMemorySize, gemm_smem);

    // CSR build
    k_zero_counts<<<(NN + 255) / 256, 256>>>();
    k_hist<<<(EE + 255) / 256, 256>>>(edst);
    k_scan1<<<nblk_scan, 1024>>>();
    k_scan2<<<1, 128>>>(nblk_scan);
    k_scan3<<<nblk_scan, 1024>>>();
    k_scatter<<<(EE + 255) / 256, 256>>>(esrc, edst);

    const int agg_blocks = (NN + 7) / 8;             // warp per node, 8 warps/block
    const int gemm_blocks = (NN + GEMM_BM - 1) / GEMM_BM;

    // Layer 0
    k_agg128<<<agg_blocks, 256>>>(x, agg);
    k_gemm<true><<<gemm_blocks, 256, gemm_smem>>>(agg, x, wl0, wr0, b0, h1);
    // Layer 1
    k_agg128<<<agg_blocks, 256>>>(h1, agg);
    k_gemm<true><<<gemm_blocks, 256, gemm_smem>>>(agg, h1, wl1, wr1, b1, h2);
    // Layer 2 (project first, aggregate 2-dim, softmax)
    k_proj2<<<agg_blocks, 256>>>(h2, wl2, wr2);
    k_final<<<agg_blocks, 256>>>(b2, out);
}

// round 3
// speedup vs baseline: 1.5519x; 1.5519x over previous
#include <cuda_runtime.h>
#include <cuda_bf16.h>
#include <cstdint>

// Problem constants (fixed by the dataset)
#define NN 100000
#define EE 1600000
#define DH 128

// ---------------- scratch (device globals; no allocation allowed) -------------
__device__ float g_agg[NN * DH];
__device__ float g_h1[NN * DH];
__device__ float g_h2[NN * DH];
__device__ int   g_counts[NN];
__device__ int   g_row[NN + 1];
__device__ int   g_cursor[NN];
__device__ int   g_csr[EE];
__device__ int   g_bsums[128];
__device__ int   g_boffs[128];
__device__ float g_invdeg[NN];
__device__ float g_pl[NN * 2];
__device__ float g_pr[NN * 2];

// ---------------- CSR build --------------------------------------------------
__global__ void k_zero_counts() {
    int i = blockIdx.x * blockDim.x + threadIdx.x;
    if (i < NN) g_counts[i] = 0;
}

__global__ void k_hist(const int* __restrict__ dst) {
    int e = blockIdx.x * blockDim.x + threadIdx.x;
    if (e < EE) atomicAdd(&g_counts[dst[e]], 1);
}

// scan phase 1: per-block exclusive scan of 1024 counts
__global__ void k_scan1() {
    __shared__ int sd[1024];
    int t = threadIdx.x;
    int g = blockIdx.x * 1024 + t;
    int v = (g < NN) ? g_counts[g] : 0;
    sd[t] = v;
    __syncthreads();
    #pragma unroll
    for (int off = 1; off < 1024; off <<= 1) {
        int x = (t >= off) ? sd[t - off] : 0;
        __syncthreads();
        sd[t] += x;
        __syncthreads();
    }
    if (g < NN) g_row[g] = sd[t] - v;   // exclusive
    if (t == 1023) g_bsums[blockIdx.x] = sd[t];
}

// scan phase 2: scan of per-block sums (98 blocks -> pad to 128)
__global__ void k_scan2(int nblk) {
    __shared__ int sd[128];
    int t = threadIdx.x;
    int v = (t < nblk) ? g_bsums[t] : 0;
    sd[t] = v;
    __syncthreads();
    #pragma unroll
    for (int off = 1; off < 128; off <<= 1) {
        int x = (t >= off) ? sd[t - off] : 0;
        __syncthreads();
        sd[t] += x;
        __syncthreads();
    }
    g_boffs[t] = sd[t] - v;             // exclusive
}

// scan phase 3: add block offsets, init cursor, inv_deg
__global__ void k_scan3() {
    int t = threadIdx.x;
    int g = blockIdx.x * 1024 + t;
    if (g < NN) {
        int r = g_row[g] + g_boffs[blockIdx.x];
        g_row[g] = r;
        g_cursor[g] = r;
        int c = g_counts[g];
        g_invdeg[g] = 1.0f / (float)(c > 0 ? c : 1);
    }
    if (blockIdx.x == 0 && t == 0) g_row[NN] = EE;
}

__global__ void k_scatter(const int* __restrict__ src, const int* __restrict__ dst) {
    int e = blockIdx.x * blockDim.x + threadIdx.x;
    if (e < EE) {
        int d = dst[e];
        int pos = atomicAdd(&g_cursor[d], 1);
        g_csr[pos] = src[e];
    }
}

// ---------------- mean aggregation (128-dim), warp per dst node ---------------
__global__ void k_agg128(const float* __restrict__ hin, float* __restrict__ aggout) {
    int warp = (blockIdx.x * blockDim.x + threadIdx.x) >> 5;
    int lane = threadIdx.x & 31;
    if (warp >= NN) return;
    int s0 = g_row[warp];
    int s1 = g_row[warp + 1];
    float4 acc0 = make_float4(0.f, 0.f, 0.f, 0.f);
    float4 acc1 = make_float4(0.f, 0.f, 0.f, 0.f);
    int e = s0;
    for (; e + 1 < s1; e += 2) {
        int a = g_csr[e];
        int b = g_csr[e + 1];
        float4 va = *(const float4*)(hin + (size_t)a * DH + lane * 4);
        float4 vb = *(const float4*)(hin + (size_t)b * DH + lane * 4);
        acc0.x += va.x; acc0.y += va.y; acc0.z += va.z; acc0.w += va.w;
        acc1.x += vb.x; acc1.y += vb.y; acc1.z += vb.z; acc1.w += vb.w;
    }
    if (e < s1) {
        int a = g_csr[e];
        float4 va = *(const float4*)(hin + (size_t)a * DH + lane * 4);
        acc0.x += va.x; acc0.y += va.y; acc0.z += va.z; acc0.w += va.w;
    }
    float sc = g_invdeg[warp];
    float4 o;
    o.x = (acc0.x + acc1.x) * sc;
    o.y = (acc0.y + acc1.y) * sc;
    o.z = (acc0.z + acc1.z) * sc;
    o.w = (acc0.w + acc1.w) * sc;
    *(float4*)(aggout + (size_t)warp * DH + lane * 4) = o;
}

// ---------------- tf32 tensor-core fused layer GEMM ---------------------------
// out = relu(agg@Wl^T + b + hin@Wr^T), K = 256 done as two K=128 chunks.
// Block tile: M=128 nodes x N=128 feats, 8 warps (4 M-warps x 2 N-warps).
// Each warp: 32 rows x 64 cols = 2 (m16) x 8 (n8) mma tiles, k8 steps.
#define XSTRIDE 132   // bank = 4g+t  -> conflict-free A-fragment reads
#define WSTRIDE 136   // bank = 8t+g  -> conflict-free B-fragment reads

__device__ __forceinline__ uint32_t f2tf32(float f) {
    uint32_t r;
    asm("cvt.rna.tf32.f32 %0, %1;" : "=r"(r) : "f"(f));
    return r;
}

__device__ __forceinline__ void mma_tf32(float* c, const uint32_t* a, const uint32_t* b) {
    asm volatile(
        "mma.sync.aligned.m16n8k8.row.col.f32.tf32.tf32.f32 "
        "{%0,%1,%2,%3}, {%4,%5,%6,%7}, {%8,%9}, {%0,%1,%2,%3};"
        : "+f"(c[0]), "+f"(c[1]), "+f"(c[2]), "+f"(c[3])
        : "r"(a[0]), "r"(a[1]), "r"(a[2]), "r"(a[3]), "r"(b[0]), "r"(b[1]));
}

template <bool RELU>
__global__ void __launch_bounds__(256) k_gemm_tf32(
    const float* __restrict__ agg, const float* __restrict__ hin,
    const float* __restrict__ wl, const float* __restrict__ wr,
    const float* __restrict__ bias, float* __restrict__ hout) {
    extern __shared__ uint32_t sm[];
    uint32_t* sW = sm;                    // [128][WSTRIDE]
    uint32_t* sX = sm + 128 * WSTRIDE;    // [128][XSTRIDE]

    int tid = threadIdx.x;
    int lane = tid & 31, wid = tid >> 5;
    int g = lane >> 2, t = lane & 3;
    int mw = wid & 3, nw = wid >> 2;
    int nodeBase = blockIdx.x * 128;

    float acc[2][8][4];
    #pragma unroll
    for (int i = 0; i < 2; i++)
        #pragma unroll
        for (int j = 0; j < 8; j++)
            #pragma unroll
            for (int q = 0; q < 4; q++) acc[i][j][q] = 0.f;

    #pragma unroll
    for (int chunk = 0; chunk < 2; chunk++) {
        const float* wsrc = chunk ? wr : wl;
        const float* xsrc = chunk ? hin : agg;

        // stage W transposed: sW[k][n] = tf32(wsrc[n*128 + k])
        for (int i = tid; i < 128 * 128; i += 256) {
            int n = i >> 7, k = i & 127;
            sW[k * WSTRIDE + n] = f2tf32(wsrc[i]);
        }
        // stage X: sX[r][c] = tf32(xsrc[(nodeBase+r)*128 + c])
        for (int i = tid; i < 128 * 32; i += 256) {
            int r = i >> 5, c4 = (i & 31) * 4;
            int n = nodeBase + r;
            float4 v = make_float4(0.f, 0.f, 0.f, 0.f);
            if (n < NN) v = *(const float4*)(xsrc + (size_t)n * DH + c4);
            uint32_t* p = &sX[r * XSTRIDE + c4];
            p[0] = f2tf32(v.x); p[1] = f2tf32(v.y);
            p[2] = f2tf32(v.z); p[3] = f2tf32(v.w);
        }
        __syncthreads();

        #pragma unroll
        for (int ks = 0; ks < 16; ks++) {
            int k0 = ks * 8;
            uint32_t a[2][4], b[8][2];
            #pragma unroll
            for (int i = 0; i < 2; i++) {
                int row = mw * 32 + i * 16 + g;
                a[i][0] = sX[row * XSTRIDE + k0 + t];
                a[i][1] = sX[(row + 8) * XSTRIDE + k0 + t];
                a[i][2] = sX[row * XSTRIDE + k0 + t + 4];
                a[i][3] = sX[(row + 8) * XSTRIDE + k0 + t + 4];
            }
            #pragma unroll
            for (int j = 0; j < 8; j++) {
                int col = nw * 64 + j * 8 + g;
                b[j][0] = sW[(k0 + t) * WSTRIDE + col];
                b[j][1] = sW[(k0 + t + 4) * WSTRIDE + col];
            }
            #pragma unroll
            for (int i = 0; i < 2; i++)
                #pragma unroll
                for (int j = 0; j < 8; j++)
                    mma_tf32(acc[i][j], a[i], b[j]);
        }
        __syncthreads();
    }

    // epilogue: bias + relu, c0/c1 -> (row, 2t|2t+1), c2/c3 -> (row+8, ...)
    #pragma unroll
    for (int i = 0; i < 2; i++) {
        int row0 = nodeBase + mw * 32 + i * 16 + g;
        #pragma unroll
        for (int j = 0; j < 8; j++) {
            int col = nw * 64 + j * 8 + 2 * t;
            float2 bb = *(const float2*)(bias + col);
            float2 v0, v1;
            v0.x = acc[i][j][0] + bb.x; v0.y = acc[i][j][1] + bb.y;
            v1.x = acc[i][j][2] + bb.x; v1.y = acc[i][j][3] + bb.y;
            if (RELU) {
                v0.x = fmaxf(v0.x, 0.f); v0.y = fmaxf(v0.y, 0.f);
                v1.x = fmaxf(v1.x, 0.f); v1.y = fmaxf(v1.y, 0.f);
            }
            if (row0 < NN)     *(float2*)(hout + (size_t)row0 * DH + col) = v0;
            if (row0 + 8 < NN) *(float2*)(hout + (size_t)(row0 + 8) * DH + col) = v1;
        }
    }
}

// ---------------- layer 2: project h2 -> [N,2] for both paths -----------------
__global__ void k_proj2(const float* __restrict__ h2, const float* __restrict__ wl2,
                        const float* __restrict__ wr2) {
    int warp = (blockIdx.x * blockDim.x + threadIdx.x) >> 5;
    int lane = threadIdx.x & 31;
    if (warp >= NN) return;
    float4 hv = *(const float4*)(h2 + (size_t)warp * DH + lane * 4);
    float4 a0 = *(const float4*)(wl2 + lane * 4);
    float4 a1 = *(const float4*)(wl2 + 128 + lane * 4);
    float4 r0 = *(const float4*)(wr2 + lane * 4);
    float4 r1 = *(const float4*)(wr2 + 128 + lane * 4);
    float d0 = hv.x * a0.x + hv.y * a0.y + hv.z * a0.z + hv.w * a0.w;
    float d1 = hv.x * a1.x + hv.y * a1.y + hv.z * a1.z + hv.w * a1.w;
    float d2 = hv.x * r0.x + hv.y * r0.y + hv.z * r0.z + hv.w * r0.w;
    float d3 = hv.x * r1.x + hv.y * r1.y + hv.z * r1.z + hv.w * r1.w;
    #pragma unroll
    for (int o = 16; o; o >>= 1) {
        d0 += __shfl_xor_sync(0xffffffffu, d0, o);
        d1 += __shfl_xor_sync(0xffffffffu, d1, o);
        d2 += __shfl_xor_sync(0xffffffffu, d2, o);
        d3 += __shfl_xor_sync(0xffffffffu, d3, o);
    }
    if (lane == 0) {
        g_pl[warp * 2 + 0] = d0;
        g_pl[warp * 2 + 1] = d1;
        g_pr[warp * 2 + 0] = d2;
        g_pr[warp * 2 + 1] = d3;
    }
}

// ---------------- layer 2 aggregation (2-dim) + bias + log_softmax ------------
__global__ void k_final(const float* __restrict__ b2, float* __restrict__ out) {
    int warp = (blockIdx.x * blockDim.x + threadIdx.x) >> 5;
    int lane = threadIdx.x & 31;
    if (warp >= NN) return;
    int s0 = g_row[warp];
    int s1 = g_row[warp + 1];
    float a0 = 0.f, a1 = 0.f;
    for (int e = s0 + lane; e < s1; e += 32) {
        int s = g_csr[e];
        float2 v = *(const float2*)&g_pl[s * 2];
        a0 += v.x;
        a1 += v.y;
    }
    #pragma unroll
    for (int o = 16; o; o >>= 1) {
        a0 += __shfl_xor_sync(0xffffffffu, a0, o);
        a1 += __shfl_xor_sync(0xffffffffu, a1, o);
    }
    if (lane == 0) {
        float inv = g_invdeg[warp];
        float o0 = a0 * inv + b2[0] + g_pr[warp * 2 + 0];
        float o1 = a1 * inv + b2[1] + g_pr[warp * 2 + 1];
        float m = fmaxf(o0, o1);
        float ls = m + logf(expf(o0 - m) + expf(o1 - m));
        out[warp * 2 + 0] = o0 - ls;
        out[warp * 2 + 1] = o1 - ls;
    }
}

// ---------------- launch -----------------------------------------------------
extern "C" void kernel_launch(void* const* d_in, const int* in_sizes, int n_in,
                              void* d_out, int out_size) {
    const float* x    = (const float*)d_in[0];
    const float* wl0  = (const float*)d_in[1];
    const float* b0   = (const float*)d_in[2];
    const float* wr0  = (const float*)d_in[3];
    const float* wl1  = (const float*)d_in[4];
    const float* b1   = (const float*)d_in[5];
    const float* wr1  = (const float*)d_in[6];
    const float* wl2  = (const float*)d_in[7];
    const float* b2   = (const float*)d_in[8];
    const float* wr2  = (const float*)d_in[9];
    const int* esrc   = (const int*)d_in[10];
    const int* edst   = (const int*)d_in[11];
    float* out        = (float*)d_out;

    float* agg; cudaGetSymbolAddress((void**)&agg, g_agg);
    float* h1;  cudaGetSymbolAddress((void**)&h1, g_h1);
    float* h2;  cudaGetSymbolAddress((void**)&h2, g_h2);

    const int nblk_scan = (NN + 1023) / 1024;        // 98
    const int gemm_smem = (128 * WSTRIDE + 128 * XSTRIDE) * (int)sizeof(uint32_t);
    cudaFuncSetAttribute(k_gemm_tf32<true>, cudaFuncAttributeMaxDynamicSharedMemorySize, gemm_smem);

    // CSR build
    k_zero_counts<<<(NN + 255) / 256, 256>>>();
    k_hist<<<(EE + 255) / 256, 256>>>(edst);
    k_scan1<<<nblk_scan, 1024>>>();
    k_scan2<<<1, 128>>>(nblk_scan);
    k_scan3<<<nblk_scan, 1024>>>();
    k_scatter<<<(EE + 255) / 256, 256>>>(esrc, edst);

    const int agg_blocks = (NN + 7) / 8;             // warp per node, 8 warps/block
    const int gemm_blocks = (NN + 127) / 128;        // 782

    // Layer 0
    k_agg128<<<agg_blocks, 256>>>(x, agg);
    k_gemm_tf32<true><<<gemm_blocks, 256, gemm_smem>>>(agg, x, wl0, wr0, b0, h1);
    // Layer 1
    k_agg128<<<agg_blocks, 256>>>(h1, agg);
    k_gemm_tf32<true><<<gemm_blocks, 256, gemm_smem>>>(agg, h1, wl1, wr1, b1, h2);
    // Layer 2 (project first, aggregate 2-dim, softmax)
    k_proj2<<<agg_blocks, 256>>>(h2, wl2, wr2);
    k_final<<<agg_blocks, 256>>>(b2, out);
}

// round 5
// speedup vs baseline: 1.6993x; 1.0950x over previous
#include <cuda_runtime.h>
#include <cuda_bf16.h>
#include <cstdint>

// Problem constants (fixed by the dataset)
#define NN 100000
#define EE 1600000
#define DH 128

// ---------------- scratch (device globals; no allocation allowed) -------------
__device__ float g_h1[NN * DH];
__device__ int   g_counts[NN];
__device__ int   g_row[NN + 1];
__device__ int   g_cursor[NN];
__device__ int   g_csr[EE];
__device__ int   g_bsums[128];
__device__ int   g_boffs[128];
__device__ float g_invdeg[NN];
__device__ float g_pl[NN * 2];
__device__ float g_pr[NN * 2];

// ---------------- CSR build --------------------------------------------------
__global__ void k_zero_counts() {
    int i = blockIdx.x * blockDim.x + threadIdx.x;
    if (i < NN) g_counts[i] = 0;
}

__global__ void k_hist(const int* __restrict__ dst) {
    int e = blockIdx.x * blockDim.x + threadIdx.x;
    if (e < EE) atomicAdd(&g_counts[dst[e]], 1);
}

__global__ void k_scan1() {
    __shared__ int sd[1024];
    int t = threadIdx.x;
    int g = blockIdx.x * 1024 + t;
    int v = (g < NN) ? g_counts[g] : 0;
    sd[t] = v;
    __syncthreads();
    #pragma unroll
    for (int off = 1; off < 1024; off <<= 1) {
        int x = (t >= off) ? sd[t - off] : 0;
        __syncthreads();
        sd[t] += x;
        __syncthreads();
    }
    if (g < NN) g_row[g] = sd[t] - v;   // exclusive
    if (t == 1023) g_bsums[blockIdx.x] = sd[t];
}

__global__ void k_scan2(int nblk) {
    __shared__ int sd[128];
    int t = threadIdx.x;
    int v = (t < nblk) ? g_bsums[t] : 0;
    sd[t] = v;
    __syncthreads();
    #pragma unroll
    for (int off = 1; off < 128; off <<= 1) {
        int x = (t >= off) ? sd[t - off] : 0;
        __syncthreads();
        sd[t] += x;
        __syncthreads();
    }
    g_boffs[t] = sd[t] - v;             // exclusive
}

__global__ void k_scan3() {
    int t = threadIdx.x;
    int g = blockIdx.x * 1024 + t;
    if (g < NN) {
        int r = g_row[g] + g_boffs[blockIdx.x];
        g_row[g] = r;
        g_cursor[g] = r;
        int c = g_counts[g];
        g_invdeg[g] = 1.0f / (float)(c > 0 ? c : 1);
    }
    if (blockIdx.x == 0 && t == 0) g_row[NN] = EE;
}

__global__ void k_scatter(const int* __restrict__ src, const int* __restrict__ dst) {
    int e = blockIdx.x * blockDim.x + threadIdx.x;
    if (e < EE) {
        int d = dst[e];
        int pos = atomicAdd(&g_cursor[d], 1);
        g_csr[pos] = src[e];
    }
}

// ---------------- fused layer: mean-agg + tf32 GEMM (+ optional projection) ---
// out = relu(mean_nbr(hin)@Wl^T + b + hin@Wr^T)
// MODE 0: write full 128-dim result to hout.
// MODE 1: also project with wl2/wr2 (output layer commuted through the mean)
//         and write only g_pl/g_pr [N,2] each; hout untouched.
// Block tile: M=128 nodes x N=128 feats, 8 warps (4 M-warps x 2 N-warps).
// K = 256 as two chunks of 128 (agg path | root path), sW staged in K=64 halves.
#define XSTRIDE 132   // A-fragment reads conflict-free
#define WSTRIDE 136   // B-fragment reads conflict-free

__device__ __forceinline__ uint32_t f2tf32(float f) {
    uint32_t r;
    asm("cvt.rna.tf32.f32 %0, %1;" : "=r"(r) : "f"(f));
    return r;
}

__device__ __forceinline__ void mma_tf32(float* c, const uint32_t* a, const uint32_t* b) {
    asm volatile(
        "mma.sync.aligned.m16n8k8.row.col.f32.tf32.tf32.f32 "
        "{%0,%1,%2,%3}, {%4,%5,%6,%7}, {%8,%9}, {%0,%1,%2,%3};"
        : "+f"(c[0]), "+f"(c[1]), "+f"(c[2]), "+f"(c[3])
        : "r"(a[0]), "r"(a[1]), "r"(a[2]), "r"(a[3]), "r"(b[0]), "r"(b[1]));
}

template <int MODE>
__global__ void __launch_bounds__(256, 2) k_layer(
    const float* __restrict__ hin,
    const float* __restrict__ wl, const float* __restrict__ wr,
    const float* __restrict__ bias, float* __restrict__ hout,
    const float* __restrict__ wl2, const float* __restrict__ wr2) {
    extern __shared__ uint32_t sm[];
    uint32_t* sW = sm;                    // [64][WSTRIDE]
    uint32_t* sX = sm + 64 * WSTRIDE;     // [128][XSTRIDE]

    int tid = threadIdx.x;
    int lane = tid & 31, wid = tid >> 5;
    int g = lane >> 2, t = lane & 3;
    int mw = wid & 3, nw = wid >> 2;
    int nodeBase = blockIdx.x * 128;

    float acc[2][8][4];
    #pragma unroll
    for (int i = 0; i < 2; i++)
        #pragma unroll
        for (int j = 0; j < 8; j++)
            #pragma unroll
            for (int q = 0; q < 4; q++) acc[i][j][q] = 0.f;

    #pragma unroll
    for (int chunk = 0; chunk < 2; chunk++) {
        const float* wsrc = chunk ? wr : wl;

        // ---- stage X for this chunk ----
        if (chunk == 0) {
            // fused mean-aggregation: warp wid handles nodes wid*16 .. wid*16+15
            for (int p = 0; p < 16; p++) {
                int r = wid * 16 + p;
                int node = nodeBase + r;
                float4 a0 = make_float4(0.f, 0.f, 0.f, 0.f);
                float4 a1 = make_float4(0.f, 0.f, 0.f, 0.f);
                if (node < NN) {
                    int s0 = g_row[node], s1 = g_row[node + 1];
                    int e = s0;
                    for (; e + 1 < s1; e += 2) {
                        int sa = g_csr[e], sb = g_csr[e + 1];
                        float4 va = *(const float4*)(hin + (size_t)sa * DH + lane * 4);
                        float4 vb = *(const float4*)(hin + (size_t)sb * DH + lane * 4);
                        a0.x += va.x; a0.y += va.y; a0.z += va.z; a0.w += va.w;
                        a1.x += vb.x; a1.y += vb.y; a1.z += vb.z; a1.w += vb.w;
                    }
                    if (e < s1) {
                        int sa = g_csr[e];
                        float4 va = *(const float4*)(hin + (size_t)sa * DH + lane * 4);
                        a0.x += va.x; a0.y += va.y; a0.z += va.z; a0.w += va.w;
                    }
                    float sc = g_invdeg[node];
                    a0.x = (a0.x + a1.x) * sc; a0.y = (a0.y + a1.y) * sc;
                    a0.z = (a0.z + a1.z) * sc; a0.w = (a0.w + a1.w) * sc;
                } else {
                    a0 = make_float4(0.f, 0.f, 0.f, 0.f);
                }
                uint32_t* px = &sX[r * XSTRIDE + lane * 4];
                px[0] = f2tf32(a0.x); px[1] = f2tf32(a0.y);
                px[2] = f2tf32(a0.z); px[3] = f2tf32(a0.w);
            }
        } else {
            // root path: coalesced rows of hin
            for (int i = tid; i < 128 * 32; i += 256) {
                int r = i >> 5, c4 = (i & 31) * 4;
                int n = nodeBase + r;
                float4 v = make_float4(0.f, 0.f, 0.f, 0.f);
                if (n < NN) v = *(const float4*)(hin + (size_t)n * DH + c4);
                uint32_t* px = &sX[r * XSTRIDE + c4];
                px[0] = f2tf32(v.x); px[1] = f2tf32(v.y);
                px[2] = f2tf32(v.z); px[3] = f2tf32(v.w);
            }
        }

        // ---- two K=64 halves of W ----
        #pragma unroll
        for (int half = 0; half < 2; half++) {
            int koff = half * 64;
            __syncthreads();   // (re)staged sX ready / previous mma done with sW
            if (half == 0 && chunk == 0) { /* first sync covers initial entry */ }
            // stage sW[k][n] = tf32(wsrc[n*128 + koff + k]), k in [0,64)
            for (int i = tid; i < 64 * 128; i += 256) {
                int n = i >> 6, k = i & 63;
                sW[k * WSTRIDE + n] = f2tf32(wsrc[n * 128 + koff + k]);
            }
            __syncthreads();

            #pragma unroll
            for (int ks = 0; ks < 8; ks++) {
                int k0 = ks * 8;
                uint32_t a[2][4], b[8][2];
                #pragma unroll
                for (int i = 0; i < 2; i++) {
                    int row = mw * 32 + i * 16 + g;
                    a[i][0] = sX[row * XSTRIDE + koff + k0 + t];
                    a[i][1] = sX[(row + 8) * XSTRIDE + koff + k0 + t];
                    a[i][2] = sX[row * XSTRIDE + koff + k0 + t + 4];
                    a[i][3] = sX[(row + 8) * XSTRIDE + koff + k0 + t + 4];
                }
                #pragma unroll
                for (int j = 0; j < 8; j++) {
                    int col = nw * 64 + j * 8 + g;
                    b[j][0] = sW[(k0 + t) * WSTRIDE + col];
                    b[j][1] = sW[(k0 + t + 4) * WSTRIDE + col];
                }
                #pragma unroll
                for (int i = 0; i < 2; i++)
                    #pragma unroll
                    for (int j = 0; j < 8; j++)
                        mma_tf32(acc[i][j], a[i], b[j]);
            }
        }
        __syncthreads();   // mma done before sX is restaged / smem reused
    }

    if (MODE == 0) {
        // epilogue: bias + relu -> hout
        #pragma unroll
        for (int i = 0; i < 2; i++) {
            int row0 = nodeBase + mw * 32 + i * 16 + g;
            #pragma unroll
            for (int j = 0; j < 8; j++) {
                int col = nw * 64 + j * 8 + 2 * t;
                float2 bb = *(const float2*)(bias + col);
                float2 v0, v1;
                v0.x = fmaxf(acc[i][j][0] + bb.x, 0.f);
                v0.y = fmaxf(acc[i][j][1] + bb.y, 0.f);
                v1.x = fmaxf(acc[i][j][2] + bb.x, 0.f);
                v1.y = fmaxf(acc[i][j][3] + bb.y, 0.f);
                if (row0 < NN)     *(float2*)(hout + (size_t)row0 * DH + col) = v0;
                if (row0 + 8 < NN) *(float2*)(hout + (size_t)(row0 + 8) * DH + col) = v1;
            }
        }
    } else {
        // epilogue: bias + relu, then project rows onto wl2/wr2 (2 outputs each).
        // Each thread holds cols {col, col+1} for 4 rows -> partial dots, then
        // reduce over the quad (t=0..3) and across the two N-warps via smem.
        float pp[4][4];
        #pragma unroll
        for (int s = 0; s < 4; s++)
            #pragma unroll
            for (int o = 0; o < 4; o++) pp[s][o] = 0.f;

        #pragma unroll
        for (int j = 0; j < 8; j++) {
            int col = nw * 64 + j * 8 + 2 * t;
            float2 bb = *(const float2*)(bias + col);
            float2 wl2a = *(const float2*)(wl2 + col);
            float2 wl2b = *(const float2*)(wl2 + 128 + col);
            float2 wr2a = *(const float2*)(wr2 + col);
            float2 wr2b = *(const float2*)(wr2 + 128 + col);
            #pragma unroll
            for (int i = 0; i < 2; i++) {
                // slot 2i:   row = mw*32 + i*16 + g      (acc[i][j][0..1])
                // slot 2i+1: row = mw*32 + i*16 + 8 + g  (acc[i][j][2..3])
                float vx = fmaxf(acc[i][j][0] + bb.x, 0.f);
                float vy = fmaxf(acc[i][j][1] + bb.y, 0.f);
                pp[2*i][0] += vx * wl2a.x + vy * wl2a.y;
                pp[2*i][1] += vx * wl2b.x + vy * wl2b.y;
                pp[2*i][2] += vx * wr2a.x + vy * wr2a.y;
                pp[2*i][3] += vx * wr2b.x + vy * wr2b.y;
                vx = fmaxf(acc[i][j][2] + bb.x, 0.f);
                vy = fmaxf(acc[i][j][3] + bb.y, 0.f);
                pp[2*i+1][0] += vx * wl2a.x + vy * wl2a.y;
                pp[2*i+1][1] += vx * wl2b.x + vy * wl2b.y;
                pp[2*i+1][2] += vx * wr2a.x + vy * wr2a.y;
                pp[2*i+1][3] += vx * wr2b.x + vy * wr2b.y;
            }
        }
        // reduce over t (lane bits 0-1)
        #pragma unroll
        for (int s = 0; s < 4; s++)
            #pragma unroll
            for (int o = 0; o < 4; o++) {
                pp[s][o] += __shfl_xor_sync(0xffffffffu, pp[s][o], 1);
                pp[s][o] += __shfl_xor_sync(0xffffffffu, pp[s][o], 2);
            }
        float* sred = (float*)sm;   // [128][8] = row x (nw*4 + o)
        if (t == 0) {
            #pragma unroll
            for (int s = 0; s < 4; s++) {
                int lr = mw * 32 + s * 8 + g;
                #pragma unroll
                for (int o = 0; o < 4; o++) sred[lr * 8 + nw * 4 + o] = pp[s][o];
            }
        }
        __syncthreads();
        if (tid < 128) {
            int node = nodeBase + tid;
            if (node < NN) {
                float pl0 = sred[tid * 8 + 0] + sred[tid * 8 + 4];
                float pl1 = sred[tid * 8 + 1] + sred[tid * 8 + 5];
                float pr0 = sred[tid * 8 + 2] + sred[tid * 8 + 6];
                float pr1 = sred[tid * 8 + 3] + sred[tid * 8 + 7];
                *(float2*)&g_pl[node * 2] = make_float2(pl0, pl1);
                *(float2*)&g_pr[node * 2] = make_float2(pr0, pr1);
            }
        }
    }
}

// ---------------- layer 2 aggregation (2-dim) + bias + log_softmax ------------
__global__ void k_final(const float* __restrict__ b2, float* __restrict__ out) {
    int warp = (blockIdx.x * blockDim.x + threadIdx.x) >> 5;
    int lane = threadIdx.x & 31;
    if (warp >= NN) return;
    int s0 = g_row[warp];
    int s1 = g_row[warp + 1];
    float a0 = 0.f, a1 = 0.f;
    for (int e = s0 + lane; e < s1; e += 32) {
        int s = g_csr[e];
        float2 v = *(const float2*)&g_pl[s * 2];
        a0 += v.x;
        a1 += v.y;
    }
    #pragma unroll
    for (int o = 16; o; o >>= 1) {
        a0 += __shfl_xor_sync(0xffffffffu, a0, o);
        a1 += __shfl_xor_sync(0xffffffffu, a1, o);
    }
    if (lane == 0) {
        float inv = g_invdeg[warp];
        float o0 = a0 * inv + b2[0] + g_pr[warp * 2 + 0];
        float o1 = a1 * inv + b2[1] + g_pr[warp * 2 + 1];
        float m = fmaxf(o0, o1);
        float ls = m + logf(expf(o0 - m) + expf(o1 - m));
        out[warp * 2 + 0] = o0 - ls;
        out[warp * 2 + 1] = o1 - ls;
    }
}

// ---------------- launch -----------------------------------------------------
extern "C" void kernel_launch(void* const* d_in, const int* in_sizes, int n_in,
                              void* d_out, int out_size) {
    const float* x    = (const float*)d_in[0];
    const float* wl0  = (const float*)d_in[1];
    const float* b0   = (const float*)d_in[2];
    const float* wr0  = (const float*)d_in[3];
    const float* wl1  = (const float*)d_in[4];
    const float* b1   = (const float*)d_in[5];
    const float* wr1  = (const float*)d_in[6];
    const float* wl2  = (const float*)d_in[7];
    const float* b2   = (const float*)d_in[8];
    const float* wr2  = (const float*)d_in[9];
    const int* esrc   = (const int*)d_in[10];
    const int* edst   = (const int*)d_in[11];
    float* out        = (float*)d_out;

    float* h1;  cudaGetSymbolAddress((void**)&h1, g_h1);

    const int nblk_scan = (NN + 1023) / 1024;        // 98
    const int layer_smem = (64 * WSTRIDE + 128 * XSTRIDE) * (int)sizeof(uint32_t); // 102400
    cudaFuncSetAttribute(k_layer<0>, cudaFuncAttributeMaxDynamicSharedMemorySize, layer_smem);
    cudaFuncSetAttribute(k_layer<1>, cudaFuncAttributeMaxDynamicSharedMemorySize, layer_smem);

    // CSR build
    k_zero_counts<<<(NN + 255) / 256, 256>>>();
    k_hist<<<(EE + 255) / 256, 256>>>(edst);
    k_scan1<<<nblk_scan, 1024>>>();
    k_scan2<<<1, 128>>>(nblk_scan);
    k_scan3<<<nblk_scan, 1024>>>();
    k_scatter<<<(EE + 255) / 256, 256>>>(esrc, edst);

    const int gemm_blocks = (NN + 127) / 128;        // 782
    const int agg_blocks = (NN + 7) / 8;

    // Layer 0: fused agg+GEMM -> h1
    k_layer<0><<<gemm_blocks, 256, layer_smem>>>(x, wl0, wr0, b0, h1, nullptr, nullptr);
    // Layer 1: fused agg+GEMM + output projection -> g_pl/g_pr (h2 never hits gmem)
    k_layer<1><<<gemm_blocks, 256, layer_smem>>>(h1, wl1, wr1, b1, nullptr, wl2, wr2);
    // Layer 2: 2-dim aggregation + bias + log_softmax
    k_final<<<agg_blocks, 256>>>(b2, out);
}

// round 6
// speedup vs baseline: 2.3098x; 1.3593x over previous
#include <cuda_runtime.h>
#include <cuda_bf16.h>
#include <cstdint>

// Problem constants (fixed by the dataset)
#define NN 100000
#define EE 1600000
#define DH 128

// ---------------- scratch (device globals; no allocation allowed) -------------
__device__ __nv_bfloat16 g_xbf[NN * DH];
__device__ __nv_bfloat16 g_h1bf[NN * DH];
__device__ uint32_t g_wp[4 * 8192];      // 4 matrices, bf16-pair packed [k2][n]
__device__ int   g_counts[NN];
__device__ int   g_row[NN + 1];
__device__ int   g_cursor[NN];
__device__ int   g_csr[EE];
__device__ int   g_bsums[128];
__device__ float g_invdeg[NN];
__device__ float g_pl[NN * 2];
__device__ float g_pr[NN * 2];

__device__ __forceinline__ uint32_t packbf(float a, float b) {
    __nv_bfloat162 h = __floats2bfloat162_rn(a, b);   // .x = a (low), .y = b (high)
    return *reinterpret_cast<uint32_t*>(&h);
}

// ---------------- prep: zero counts + cast x to bf16 + pack weights ----------
#define XBLK 25000   // ceil(NN*64 / 256)

__global__ void k_prep(const float* __restrict__ x,
                       const float* __restrict__ wl0, const float* __restrict__ wr0,
                       const float* __restrict__ wl1, const float* __restrict__ wr1) {
    int gi = blockIdx.x * 256 + threadIdx.x;
    if (blockIdx.x < XBLK) {
        if (gi < NN) g_counts[gi] = 0;
        if (gi < NN * 64) {
            float2 v = ((const float2*)x)[gi];
            reinterpret_cast<uint32_t*>(g_xbf)[gi] = packbf(v.x, v.y);
        }
    } else {
        int i = (blockIdx.x - XBLK) * 256 + threadIdx.x;   // 0..32767
        int m = i >> 13, idx = i & 8191;
        int n = idx & 127, k2 = idx >> 7;
        const float* s = (m == 0) ? wl0 : (m == 1) ? wr0 : (m == 2) ? wl1 : wr1;
        float2 v = *(const float2*)(s + n * 128 + 2 * k2);
        g_wp[m * 8192 + k2 * 128 + n] = packbf(v.x, v.y);
    }
}

// ---------------- CSR build --------------------------------------------------
__global__ void k_hist(const int* __restrict__ dst) {
    int e = blockIdx.x * blockDim.x + threadIdx.x;
    if (e < EE) atomicAdd(&g_counts[dst[e]], 1);
}

__global__ void k_scan1() {
    __shared__ int sd[1024];
    int t = threadIdx.x;
    int g = blockIdx.x * 1024 + t;
    int v = (g < NN) ? g_counts[g] : 0;
    sd[t] = v;
    __syncthreads();
    #pragma unroll
    for (int off = 1; off < 1024; off <<= 1) {
        int x = (t >= off) ? sd[t - off] : 0;
        __syncthreads();
        sd[t] += x;
        __syncthreads();
    }
    if (g < NN) g_row[g] = sd[t] - v;   // exclusive within block
    if (t == 1023) g_bsums[blockIdx.x] = sd[t];
}

// scan of block sums done redundantly per block (98 values, trivial) + finalize
__global__ void k_scan3() {
    __shared__ int sb[128];
    int t = threadIdx.x;
    if (t < 128) sb[t] = (t < 98) ? g_bsums[t] : 0;
    __syncthreads();
    #pragma unroll
    for (int off = 1; off < 128; off <<= 1) {
        int x = (t < 128 && t >= off) ? sb[t - off] : 0;
        __syncthreads();
        if (t < 128) sb[t] += x;
        __syncthreads();
    }
    int myoff = (blockIdx.x == 0) ? 0 : sb[blockIdx.x - 1];   // inclusive -> exclusive
    int g = blockIdx.x * 1024 + t;
    if (g < NN) {
        int r = g_row[g] + myoff;
        g_row[g] = r;
        g_cursor[g] = r;
        int c = g_counts[g];
        g_invdeg[g] = 1.0f / (float)(c > 0 ? c : 1);
    }
    if (blockIdx.x == 0 && t == 0) g_row[NN] = EE;
}

__global__ void k_scatter(const int* __restrict__ src, const int* __restrict__ dst) {
    int e = blockIdx.x * blockDim.x + threadIdx.x;
    if (e < EE) {
        int d = dst[e];
        int pos = atomicAdd(&g_cursor[d], 1);
        g_csr[pos] = src[e];
    }
}

// ---------------- fused layer: bf16 mean-agg + bf16 MMA (+ projection) -------
// out = relu(mean_nbr(hin)@Wl^T + b + hin@Wr^T)
// MODE 0: write 128-dim bf16 result to hout.
// MODE 1: project with wl2/wr2 -> g_pl/g_pr [N,2]; hout untouched.
// Block: M=128 x N=128, 8 warps (4 M x 2 N). K=256 as two K=128 chunks,
// mma m16n8k16 bf16, fp32 accumulate.
#define XS2 68    // uint32 (bf16x2) stride: A-frag reads conflict-free
#define WS2 136   // uint32 stride: B-frag reads conflict-free

__device__ __forceinline__ void mma_bf16(float* c, const uint32_t* a, const uint32_t* b) {
    asm volatile(
        "mma.sync.aligned.m16n8k16.row.col.f32.bf16.bf16.f32 "
        "{%0,%1,%2,%3}, {%4,%5,%6,%7}, {%8,%9}, {%0,%1,%2,%3};"
        : "+f"(c[0]), "+f"(c[1]), "+f"(c[2]), "+f"(c[3])
        : "r"(a[0]), "r"(a[1]), "r"(a[2]), "r"(a[3]), "r"(b[0]), "r"(b[1]));
}

template <int MODE>
__global__ void __launch_bounds__(256, 2) k_layer(
    const __nv_bfloat16* __restrict__ hin,
    const uint32_t* __restrict__ wpL, const uint32_t* __restrict__ wpR,
    const float* __restrict__ bias, __nv_bfloat16* __restrict__ hout,
    const float* __restrict__ wl2, const float* __restrict__ wr2) {
    extern __shared__ uint32_t sm[];
    uint32_t* sW = sm;                    // [64][WS2]
    uint32_t* sX = sm + 64 * WS2;         // [128][XS2]

    int tid = threadIdx.x;
    int lane = tid & 31, wid = tid >> 5;
    int g = lane >> 2, t = lane & 3;
    int mw = wid & 3, nw = wid >> 2;
    int nodeBase = blockIdx.x * 128;

    float acc[2][8][4];
    #pragma unroll
    for (int i = 0; i < 2; i++)
        #pragma unroll
        for (int j = 0; j < 8; j++)
            #pragma unroll
            for (int q = 0; q < 4; q++) acc[i][j][q] = 0.f;

    #pragma unroll
    for (int chunk = 0; chunk < 2; chunk++) {
        // ---- stage X ----
        if (chunk == 0) {
            // fused mean aggregation: warp wid handles rows wid*16..wid*16+15
            for (int p = 0; p < 16; p++) {
                int r = wid * 16 + p;
                int node = nodeBase + r;
                float s0f = 0.f, s1f = 0.f, s2f = 0.f, s3f = 0.f;
                if (node < NN) {
                    int e0 = g_row[node], e1 = g_row[node + 1];
                    for (int e = e0; e < e1; e++) {
                        int sa = g_csr[e];
                        uint2 va = ((const uint2*)(hin + (size_t)sa * DH))[lane];
                        float2 f0 = __bfloat1622float2(*(__nv_bfloat162*)&va.x);
                        float2 f1 = __bfloat1622float2(*(__nv_bfloat162*)&va.y);
                        s0f += f0.x; s1f += f0.y; s2f += f1.x; s3f += f1.y;
                    }
                    float sc = g_invdeg[node];
                    s0f *= sc; s1f *= sc; s2f *= sc; s3f *= sc;
                }
                sX[r * XS2 + lane * 2]     = packbf(s0f, s1f);
                sX[r * XS2 + lane * 2 + 1] = packbf(s2f, s3f);
            }
        } else {
            // root path: coalesced bf16 rows
            for (int i = tid; i < 128 * 64; i += 256) {
                int r = i >> 6, c2 = i & 63;
                int n = nodeBase + r;
                uint32_t v = 0;
                if (n < NN) v = ((const uint32_t*)hin)[(size_t)n * 64 + c2];
                sX[r * XS2 + c2] = v;
            }
        }
        // ---- stage W (pre-packed bf16 pairs, straight copy) ----
        const uint32_t* wp = chunk ? wpR : wpL;
        for (int i = tid; i < 64 * 128; i += 256) {
            int k2 = i >> 7, n = i & 127;
            sW[k2 * WS2 + n] = wp[i];
        }
        __syncthreads();

        #pragma unroll
        for (int ks = 0; ks < 8; ks++) {
            int k02 = ks * 8;   // col2 units (16 k-elements = 8 pairs)
            uint32_t a[2][4], b[8][2];
            #pragma unroll
            for (int i = 0; i < 2; i++) {
                int row = mw * 32 + i * 16 + g;
                a[i][0] = sX[row * XS2 + k02 + t];
                a[i][1] = sX[(row + 8) * XS2 + k02 + t];
                a[i][2] = sX[row * XS2 + k02 + t + 4];
                a[i][3] = sX[(row + 8) * XS2 + k02 + t + 4];
            }
            #pragma unroll
            for (int j = 0; j < 8; j++) {
                int col = nw * 64 + j * 8 + g;
                b[j][0] = sW[(k02 + t) * WS2 + col];
                b[j][1] = sW[(k02 + t + 4) * WS2 + col];
            }
            #pragma unroll
            for (int i = 0; i < 2; i++)
                #pragma unroll
                for (int j = 0; j < 8; j++)
                    mma_bf16(acc[i][j], a[i], b[j]);
        }
        __syncthreads();
    }

    if (MODE == 0) {
        // epilogue: bias + relu -> bf16 hout
        #pragma unroll
        for (int i = 0; i < 2; i++) {
            int row0 = nodeBase + mw * 32 + i * 16 + g;
            #pragma unroll
            for (int j = 0; j < 8; j++) {
                int col = nw * 64 + j * 8 + 2 * t;
                float2 bb = *(const float2*)(bias + col);
                float v0x = fmaxf(acc[i][j][0] + bb.x, 0.f);
                float v0y = fmaxf(acc[i][j][1] + bb.y, 0.f);
                float v1x = fmaxf(acc[i][j][2] + bb.x, 0.f);
                float v1y = fmaxf(acc[i][j][3] + bb.y, 0.f);
                if (row0 < NN)
                    ((uint32_t*)hout)[(size_t)row0 * 64 + (col >> 1)] = packbf(v0x, v0y);
                if (row0 + 8 < NN)
                    ((uint32_t*)hout)[(size_t)(row0 + 8) * 64 + (col >> 1)] = packbf(v1x, v1y);
            }
        }
    } else {
        // epilogue: bias + relu + project onto wl2/wr2 (fp32)
        float pp[4][4];
        #pragma unroll
        for (int s = 0; s < 4; s++)
            #pragma unroll
            for (int o = 0; o < 4; o++) pp[s][o] = 0.f;

        #pragma unroll
        for (int j = 0; j < 8; j++) {
            int col = nw * 64 + j * 8 + 2 * t;
            float2 bb = *(const float2*)(bias + col);
            float2 wl2a = *(const float2*)(wl2 + col);
            float2 wl2b = *(const float2*)(wl2 + 128 + col);
            float2 wr2a = *(const float2*)(wr2 + col);
            float2 wr2b = *(const float2*)(wr2 + 128 + col);
            #pragma unroll
            for (int i = 0; i < 2; i++) {
                float vx = fmaxf(acc[i][j][0] + bb.x, 0.f);
                float vy = fmaxf(acc[i][j][1] + bb.y, 0.f);
                pp[2*i][0] += vx * wl2a.x + vy * wl2a.y;
                pp[2*i][1] += vx * wl2b.x + vy * wl2b.y;
                pp[2*i][2] += vx * wr2a.x + vy * wr2a.y;
                pp[2*i][3] += vx * wr2b.x + vy * wr2b.y;
                vx = fmaxf(acc[i][j][2] + bb.x, 0.f);
                vy = fmaxf(acc[i][j][3] + bb.y, 0.f);
                pp[2*i+1][0] += vx * wl2a.x + vy * wl2a.y;
                pp[2*i+1][1] += vx * wl2b.x + vy * wl2b.y;
                pp[2*i+1][2] += vx * wr2a.x + vy * wr2a.y;
                pp[2*i+1][3] += vx * wr2b.x + vy * wr2b.y;
            }
        }
        #pragma unroll
        for (int s = 0; s < 4; s++)
            #pragma unroll
            for (int o = 0; o < 4; o++) {
                pp[s][o] += __shfl_xor_sync(0xffffffffu, pp[s][o], 1);
                pp[s][o] += __shfl_xor_sync(0xffffffffu, pp[s][o], 2);
            }
        float* sred = (float*)sm;   // [128][8]
        if (t == 0) {
            #pragma unroll
            for (int s = 0; s < 4; s++) {
                int lr = mw * 32 + s * 8 + g;
                #pragma unroll
                for (int o = 0; o < 4; o++) sred[lr * 8 + nw * 4 + o] = pp[s][o];
            }
        }
        __syncthreads();
        if (tid < 128) {
            int node = nodeBase + tid;
            if (node < NN) {
                float pl0 = sred[tid * 8 + 0] + sred[tid * 8 + 4];
                float pl1 = sred[tid * 8 + 1] + sred[tid * 8 + 5];
                float pr0 = sred[tid * 8 + 2] + sred[tid * 8 + 6];
                float pr1 = sred[tid * 8 + 3] + sred[tid * 8 + 7];
                *(float2*)&g_pl[node * 2] = make_float2(pl0, pl1);
                *(float2*)&g_pr[node * 2] = make_float2(pr0, pr1);
            }
        }
    }
}

// ---------------- layer 2 aggregation (2-dim) + bias + log_softmax ------------
__global__ void k_final(const float* __restrict__ b2, float* __restrict__ out) {
    int warp = (blockIdx.x * blockDim.x + threadIdx.x) >> 5;
    int lane = threadIdx.x & 31;
    if (warp >= NN) return;
    int s0 = g_row[warp];
    int s1 = g_row[warp + 1];
    float a0 = 0.f, a1 = 0.f;
    for (int e = s0 + lane; e < s1; e += 32) {
        int s = g_csr[e];
        float2 v = *(const float2*)&g_pl[s * 2];
        a0 += v.x;
        a1 += v.y;
    }
    #pragma unroll
    for (int o = 16; o; o >>= 1) {
        a0 += __shfl_xor_sync(0xffffffffu, a0, o);
        a1 += __shfl_xor_sync(0xffffffffu, a1, o);
    }
    if (lane == 0) {
        float inv = g_invdeg[warp];
        float o0 = a0 * inv + b2[0] + g_pr[warp * 2 + 0];
        float o1 = a1 * inv + b2[1] + g_pr[warp * 2 + 1];
        float m = fmaxf(o0, o1);
        float ls = m + logf(expf(o0 - m) + expf(o1 - m));
        out[warp * 2 + 0] = o0 - ls;
        out[warp * 2 + 1] = o1 - ls;
    }
}

// ---------------- launch -----------------------------------------------------
extern "C" void kernel_launch(void* const* d_in, const int* in_sizes, int n_in,
                              void* d_out, int out_size) {
    const float* x    = (const float*)d_in[0];
    const float* wl0  = (const float*)d_in[1];
    const float* b0   = (const float*)d_in[2];
    const float* wr0  = (const float*)d_in[3];
    const float* wl1  = (const float*)d_in[4];
    const float* b1   = (const float*)d_in[5];
    const float* wr1  = (const float*)d_in[6];
    const float* wl2  = (const float*)d_in[7];
    const float* b2   = (const float*)d_in[8];
    const float* wr2  = (const float*)d_in[9];
    const int* esrc   = (const int*)d_in[10];
    const int* edst   = (const int*)d_in[11];
    float* out        = (float*)d_out;

    __nv_bfloat16* xbf;  cudaGetSymbolAddress((void**)&xbf, g_xbf);
    __nv_bfloat16* h1bf; cudaGetSymbolAddress((void**)&h1bf, g_h1bf);
    uint32_t* wp;        cudaGetSymbolAddress((void**)&wp, g_wp);

    const int nblk_scan = (NN + 1023) / 1024;        // 98
    const int layer_smem = (64 * WS2 + 128 * XS2) * (int)sizeof(uint32_t);  // 69632
    cudaFuncSetAttribute(k_layer<0>, cudaFuncAttributeMaxDynamicSharedMemorySize, layer_smem);
    cudaFuncSetAttribute(k_layer<1>, cudaFuncAttributeMaxDynamicSharedMemorySize, layer_smem);

    const int gemm_blocks = (NN + 127) / 128;        // 782
    const int agg_blocks = (NN + 7) / 8;

    // 1: prep (zero counts + cast x + pack weights)
    k_prep<<<XBLK + 128, 256>>>(x, wl0, wr0, wl1, wr1);
    // 2-5: CSR build
    k_hist<<<(EE + 255) / 256, 256>>>(edst);
    k_scan1<<<nblk_scan, 1024>>>();
    k_scan3<<<nblk_scan, 1024>>>();
    k_scatter<<<(EE + 255) / 256, 256>>>(esrc, edst);
    // 6: Layer 0 fused agg+GEMM -> h1 (bf16)   [ncu -s 5 captures this]
    k_layer<0><<<gemm_blocks, 256, layer_smem>>>(xbf, wp, wp + 8192, b0, h1bf, nullptr, nullptr);
    // 7: Layer 1 fused agg+GEMM + output projection -> g_pl/g_pr
    k_layer<1><<<gemm_blocks, 256, layer_smem>>>(h1bf, wp + 16384, wp + 24576, b1, nullptr, wl2, wr2);
    // 8: Layer 2: 2-dim aggregation + bias + log_softmax
    k_final<<<agg_blocks, 256>>>(b2, out);
}